// round 1
// baseline (speedup 1.0000x reference)
#include <cuda_runtime.h>
#include <cuda_bf16.h>
#include <cstdint>

#define LSEQ  65536
#define HEADS 8
#define DIM   32
#define BS    128
#define NB    (LSEQ / BS)

#define QS_STRIDE 36   // floats; stride % 32 == 4 -> conflict-free fragment LDS
#define PS_STRIDE 68   // floats; stride % 32 == 4
#define SMEM_FLOATS (3 * 128 * QS_STRIDE + 128 * PS_STRIDE)
#define SMEM_BYTES  (SMEM_FLOATS * 4)

// round-to-nearest fp32 -> tf32 (kept in 32-bit container)
__device__ __forceinline__ uint32_t f2tf(float x) {
    uint32_t u;
    asm("cvt.rna.tf32.f32 %0, %1;" : "=r"(u) : "f"(x));
    return u;
}

__device__ __forceinline__ void mma_tf32(float* d,
                                         uint32_t a0, uint32_t a1, uint32_t a2, uint32_t a3,
                                         uint32_t b0, uint32_t b1) {
    asm volatile("mma.sync.aligned.m16n8k8.row.col.f32.tf32.tf32.f32 "
                 "{%0,%1,%2,%3}, {%4,%5,%6,%7}, {%8,%9}, {%0,%1,%2,%3};"
                 : "+f"(d[0]), "+f"(d[1]), "+f"(d[2]), "+f"(d[3])
                 : "r"(a0), "r"(a1), "r"(a2), "r"(a3), "r"(b0), "r"(b1));
}

__global__ void __launch_bounds__(256, 2)
bucket_attn_kernel(const float* __restrict__ Q, const float* __restrict__ K,
                   const float* __restrict__ V, const int* __restrict__ scope,
                   float* __restrict__ O) {
    extern __shared__ float smem[];
    float* Qs = smem;                      // [128][36]
    float* Ks = Qs + 128 * QS_STRIDE;      // [128][36]
    float* Vs = Ks + 128 * QS_STRIDE;      // [128][36]
    float* Ps = Vs + 128 * QS_STRIDE;      // [128][68]  (64 key cols per half)

    const int bucket = blockIdx.x;
    const int h      = blockIdx.y;
    const int b      = blockIdx.z;
    const int tid    = threadIdx.x;

    // bucket scope -> local [lo, hi) over positions 0..127
    const int sidx = (b * NB + bucket) * 2;
    const int lo = scope[sidx]     - bucket * BS;
    const int hi = scope[sidx + 1] - bucket * BS;

    const float scale = 0.17677669529663687f;  // 1/sqrt(32)

    // element (row i, d) lives at ((b*L + bucket*128 + i)*H + h)*32 + d
    const size_t base = ((size_t)(b * LSEQ + bucket * BS) * HEADS + h) * DIM;
    const float4* Qg = (const float4*)(Q + base);
    const float4* Kg = (const float4*)(K + base);
    const float4* Vg = (const float4*)(V + base);
    const int rowstride4 = HEADS * DIM / 4;  // 64 float4 between rows

    // ---- Stage Q,K,V into SMEM (tf32-rounded; Q pre-scaled) ----
    #pragma unroll
    for (int it = 0; it < 4; it++) {
        int idx = tid + it * 256;        // 0..1023 (128 rows x 8 float4)
        int row = idx >> 3, c4 = idx & 7;
        float4 q = Qg[row * rowstride4 + c4];
        float4 k = Kg[row * rowstride4 + c4];
        float4 v = Vg[row * rowstride4 + c4];
        float* qd = Qs + row * QS_STRIDE + c4 * 4;
        float* kd = Ks + row * QS_STRIDE + c4 * 4;
        float* vd = Vs + row * QS_STRIDE + c4 * 4;
        qd[0] = __uint_as_float(f2tf(q.x * scale));
        qd[1] = __uint_as_float(f2tf(q.y * scale));
        qd[2] = __uint_as_float(f2tf(q.z * scale));
        qd[3] = __uint_as_float(f2tf(q.w * scale));
        kd[0] = __uint_as_float(f2tf(k.x));
        kd[1] = __uint_as_float(f2tf(k.y));
        kd[2] = __uint_as_float(f2tf(k.z));
        kd[3] = __uint_as_float(f2tf(k.w));
        vd[0] = __uint_as_float(f2tf(v.x));
        vd[1] = __uint_as_float(f2tf(v.y));
        vd[2] = __uint_as_float(f2tf(v.z));
        vd[3] = __uint_as_float(f2tf(v.w));
    }
    __syncthreads();

    const int lane = tid & 31;
    const int w    = tid >> 5;
    const int gid  = lane >> 2;   // 0..7
    const int tig  = lane & 3;    // 0..3
    const int r0   = w * 16 + gid;  // this lane's rows: r0 and r0+8

    // ---- QK^T : scores[16 rows][128 cols], per-warp ----
    float sacc[16][4];
    #pragma unroll
    for (int ct = 0; ct < 16; ct++)
        #pragma unroll
        for (int j = 0; j < 4; j++) sacc[ct][j] = 0.f;

    #pragma unroll
    for (int k = 0; k < 4; k++) {
        int kc = k * 8 + tig;
        uint32_t a0 = __float_as_uint(Qs[r0 * QS_STRIDE + kc]);
        uint32_t a1 = __float_as_uint(Qs[(r0 + 8) * QS_STRIDE + kc]);
        uint32_t a2 = __float_as_uint(Qs[r0 * QS_STRIDE + kc + 4]);
        uint32_t a3 = __float_as_uint(Qs[(r0 + 8) * QS_STRIDE + kc + 4]);
        #pragma unroll
        for (int ct = 0; ct < 16; ct++) {
            int kr = ct * 8 + gid;
            uint32_t b0 = __float_as_uint(Ks[kr * QS_STRIDE + kc]);
            uint32_t b1 = __float_as_uint(Ks[kr * QS_STRIDE + kc + 4]);
            mma_tf32(sacc[ct], a0, a1, a2, a3, b0, b1);
        }
    }

    // ---- masked softmax (unnormalized exp; exact fp32 row sums) ----
    float m0 = -1e30f, m1 = -1e30f;
    #pragma unroll
    for (int ct = 0; ct < 16; ct++) {
        int c = ct * 8 + 2 * tig;
        bool v0 = (c >= lo) && (c < hi);
        bool v1 = (c + 1 >= lo) && (c + 1 < hi);
        if (v0) { m0 = fmaxf(m0, sacc[ct][0]); m1 = fmaxf(m1, sacc[ct][2]); }
        if (v1) { m0 = fmaxf(m0, sacc[ct][1]); m1 = fmaxf(m1, sacc[ct][3]); }
    }
    m0 = fmaxf(m0, __shfl_xor_sync(0xffffffffu, m0, 1));
    m0 = fmaxf(m0, __shfl_xor_sync(0xffffffffu, m0, 2));
    m1 = fmaxf(m1, __shfl_xor_sync(0xffffffffu, m1, 1));
    m1 = fmaxf(m1, __shfl_xor_sync(0xffffffffu, m1, 2));

    float l0 = 0.f, l1 = 0.f;
    #pragma unroll
    for (int ct = 0; ct < 16; ct++) {
        int c = ct * 8 + 2 * tig;
        bool v0 = (c >= lo) && (c < hi);
        bool v1 = (c + 1 >= lo) && (c + 1 < hi);
        float e0 = v0 ? __expf(sacc[ct][0] - m0) : 0.f;
        float e1 = v1 ? __expf(sacc[ct][1] - m0) : 0.f;
        float e2 = v0 ? __expf(sacc[ct][2] - m1) : 0.f;
        float e3 = v1 ? __expf(sacc[ct][3] - m1) : 0.f;
        l0 += e0 + e1;
        l1 += e2 + e3;
        sacc[ct][0] = e0; sacc[ct][1] = e1; sacc[ct][2] = e2; sacc[ct][3] = e3;
    }
    l0 += __shfl_xor_sync(0xffffffffu, l0, 1);
    l0 += __shfl_xor_sync(0xffffffffu, l0, 2);
    l1 += __shfl_xor_sync(0xffffffffu, l1, 1);
    l1 += __shfl_xor_sync(0xffffffffu, l1, 2);

    // ---- P @ V via SMEM round-trip, two 64-key halves (warp-private rows) ----
    float oacc[4][4];
    #pragma unroll
    for (int nt = 0; nt < 4; nt++)
        #pragma unroll
        for (int j = 0; j < 4; j++) oacc[nt][j] = 0.f;

    #pragma unroll
    for (int half = 0; half < 2; half++) {
        #pragma unroll
        for (int ct = 0; ct < 8; ct++) {
            int g = ct + 8 * half;
            int c = ct * 8 + 2 * tig;
            Ps[r0 * PS_STRIDE + c]           = __uint_as_float(f2tf(sacc[g][0]));
            Ps[r0 * PS_STRIDE + c + 1]       = __uint_as_float(f2tf(sacc[g][1]));
            Ps[(r0 + 8) * PS_STRIDE + c]     = __uint_as_float(f2tf(sacc[g][2]));
            Ps[(r0 + 8) * PS_STRIDE + c + 1] = __uint_as_float(f2tf(sacc[g][3]));
        }
        __syncwarp();
        #pragma unroll
        for (int ks = 0; ks < 8; ks++) {
            int kc = ks * 8 + tig;  // local col in Ps
            uint32_t a0 = __float_as_uint(Ps[r0 * PS_STRIDE + kc]);
            uint32_t a1 = __float_as_uint(Ps[(r0 + 8) * PS_STRIDE + kc]);
            uint32_t a2 = __float_as_uint(Ps[r0 * PS_STRIDE + kc + 4]);
            uint32_t a3 = __float_as_uint(Ps[(r0 + 8) * PS_STRIDE + kc + 4]);
            int vr = half * 64 + ks * 8 + tig;  // global key row in Vs
            #pragma unroll
            for (int nt = 0; nt < 4; nt++) {
                uint32_t b0 = __float_as_uint(Vs[vr * QS_STRIDE + nt * 8 + gid]);
                uint32_t b1 = __float_as_uint(Vs[(vr + 4) * QS_STRIDE + nt * 8 + gid]);
                mma_tf32(oacc[nt], a0, a1, a2, a3, b0, b1);
            }
        }
        __syncwarp();
    }

    // ---- normalize, mask invalid queries, write out ----
    float s0 = ((r0 >= lo) && (r0 < hi))         ? __frcp_rn(l0) : 0.f;
    float s1 = ((r0 + 8 >= lo) && (r0 + 8 < hi)) ? __frcp_rn(l1) : 0.f;
    float* O0 = O + base + (size_t)r0 * (HEADS * DIM);
    float* O1 = O + base + (size_t)(r0 + 8) * (HEADS * DIM);
    #pragma unroll
    for (int nt = 0; nt < 4; nt++) {
        int c = nt * 8 + 2 * tig;
        float2 o0 = make_float2(oacc[nt][0] * s0, oacc[nt][1] * s0);
        float2 o1 = make_float2(oacc[nt][2] * s1, oacc[nt][3] * s1);
        *(float2*)(O0 + c) = o0;
        *(float2*)(O1 + c) = o1;
    }
}

extern "C" void kernel_launch(void* const* d_in, const int* in_sizes, int n_in,
                              void* d_out, int out_size) {
    const float* Q     = (const float*)d_in[0];
    const float* K     = (const float*)d_in[1];
    const float* V     = (const float*)d_in[2];
    const int*   scope = (const int*)d_in[3];
    (void)n_in; (void)out_size;

    int B = in_sizes[0] / (LSEQ * HEADS * DIM);  // = 2

    cudaFuncSetAttribute(bucket_attn_kernel,
                         cudaFuncAttributeMaxDynamicSharedMemorySize, SMEM_BYTES);

    dim3 grid(NB, HEADS, B);
    bucket_attn_kernel<<<grid, 256, SMEM_BYTES>>>(Q, K, V, scope, (float*)d_out);
}

// round 3
// speedup vs baseline: 1.4178x; 1.4178x over previous
#include <cuda_runtime.h>
#include <cstdint>

#define LSEQ  65536
#define HEADS 8
#define DIM   32
#define BS    128
#define NB    (LSEQ / BS)

#define QK_STRIDE 40   // floats; fragment .64 loads + staging .128 conflict-free
#define V_STRIDE  36   // floats; scalar PV B-loads conflict-free
#define SMEM_FLOATS (2 * 128 * QK_STRIDE + 128 * V_STRIDE)
#define SMEM_BYTES  (SMEM_FLOATS * 4)

// round-to-nearest fp32 -> tf32 (kept in 32-bit container)
__device__ __forceinline__ uint32_t f2tf(float x) {
    uint32_t u;
    asm("cvt.rna.tf32.f32 %0, %1;" : "=r"(u) : "f"(x));
    return u;
}

__device__ __forceinline__ void mma_tf32(float* d,
                                         uint32_t a0, uint32_t a1, uint32_t a2, uint32_t a3,
                                         uint32_t b0, uint32_t b1) {
    asm volatile("mma.sync.aligned.m16n8k8.row.col.f32.tf32.tf32.f32 "
                 "{%0,%1,%2,%3}, {%4,%5,%6,%7}, {%8,%9}, {%0,%1,%2,%3};"
                 : "+f"(d[0]), "+f"(d[1]), "+f"(d[2]), "+f"(d[3])
                 : "r"(a0), "r"(a1), "r"(a2), "r"(a3), "r"(b0), "r"(b1));
}

__global__ void __launch_bounds__(256, 2)
bucket_attn_kernel(const float* __restrict__ Q, const float* __restrict__ K,
                   const float* __restrict__ V, const int* __restrict__ scope,
                   float* __restrict__ O) {
    extern __shared__ float smem[];
    float* Qs = smem;                       // [128][40]
    float* Ks = Qs + 128 * QK_STRIDE;       // [128][40]
    float* Vs = Ks + 128 * QK_STRIDE;       // [128][36]  natural [key][d]

    const int bucket = blockIdx.x;
    const int h      = blockIdx.y;
    const int b      = blockIdx.z;
    const int tid    = threadIdx.x;

    const int sidx = (b * NB + bucket) * 2;
    const int lo = scope[sidx]     - bucket * BS;
    const int hi = scope[sidx + 1] - bucket * BS;

    const float scale = 0.17677669529663687f;  // 1/sqrt(32)

    const size_t base = ((size_t)(b * LSEQ + bucket * BS) * HEADS + h) * DIM;
    const float4* Qg = (const float4*)(Q + base);
    const float4* Kg = (const float4*)(K + base);
    const float4* Vg = (const float4*)(V + base);
    const int rs4 = HEADS * DIM / 4;  // 64 float4 between rows

    // ---- Stage Q,K,V into SMEM (tf32-rounded; Q pre-scaled); vectorized STS.128 ----
    #pragma unroll
    for (int it = 0; it < 4; it++) {
        int idx = tid + it * 256;        // 0..1023 (128 rows x 8 float4)
        int row = idx >> 3, c4 = idx & 7;
        float4 q = Qg[row * rs4 + c4];
        float4 k = Kg[row * rs4 + c4];
        float4 v = Vg[row * rs4 + c4];
        uint4 qt = make_uint4(f2tf(q.x * scale), f2tf(q.y * scale),
                              f2tf(q.z * scale), f2tf(q.w * scale));
        uint4 kt = make_uint4(f2tf(k.x), f2tf(k.y), f2tf(k.z), f2tf(k.w));
        uint4 vt = make_uint4(f2tf(v.x), f2tf(v.y), f2tf(v.z), f2tf(v.w));
        *(uint4*)(Qs + row * QK_STRIDE + c4 * 4) = qt;
        *(uint4*)(Ks + row * QK_STRIDE + c4 * 4) = kt;
        *(uint4*)(Vs + row * V_STRIDE  + c4 * 4) = vt;
    }
    __syncthreads();

    const int lane = tid & 31;
    const int w    = tid >> 5;
    const int gid  = lane >> 2;     // 0..7
    const int tig  = lane & 3;      // 0..3
    const int r0   = w * 16 + gid;  // this lane's rows: r0 and r0+8

    // ---- QK^T : scores[16 rows][128 cols], per-warp ----
    // k-permutation: k_logical t <-> col 8ks+2t, t+4 <-> 8ks+2t+1 (both operands)
    float sacc[16][4];
    #pragma unroll
    for (int ct = 0; ct < 16; ct++)
        #pragma unroll
        for (int j = 0; j < 4; j++) sacc[ct][j] = 0.f;

    #pragma unroll
    for (int ks = 0; ks < 4; ks++) {
        int kc = ks * 8 + 2 * tig;
        float2 alo = *(const float2*)(Qs + r0 * QK_STRIDE + kc);        // (a0, a2)
        float2 ahi = *(const float2*)(Qs + (r0 + 8) * QK_STRIDE + kc);  // (a1, a3)
        uint32_t a0 = __float_as_uint(alo.x), a2 = __float_as_uint(alo.y);
        uint32_t a1 = __float_as_uint(ahi.x), a3 = __float_as_uint(ahi.y);
        #pragma unroll
        for (int ct = 0; ct < 16; ct++) {
            int kr = ct * 8 + gid;
            float2 bp = *(const float2*)(Ks + kr * QK_STRIDE + kc);     // (b0, b1)
            mma_tf32(sacc[ct], a0, a1, a2, a3,
                     __float_as_uint(bp.x), __float_as_uint(bp.y));
        }
    }

    // ---- masked softmax (quad shuffles; unnormalized exp; exact fp32 sums) ----
    float m0 = -1e30f, m1 = -1e30f;
    #pragma unroll
    for (int ct = 0; ct < 16; ct++) {
        int c = ct * 8 + 2 * tig;
        bool v0 = (c >= lo) && (c < hi);
        bool v1 = (c + 1 >= lo) && (c + 1 < hi);
        if (v0) { m0 = fmaxf(m0, sacc[ct][0]); m1 = fmaxf(m1, sacc[ct][2]); }
        if (v1) { m0 = fmaxf(m0, sacc[ct][1]); m1 = fmaxf(m1, sacc[ct][3]); }
    }
    m0 = fmaxf(m0, __shfl_xor_sync(0xffffffffu, m0, 1));
    m0 = fmaxf(m0, __shfl_xor_sync(0xffffffffu, m0, 2));
    m1 = fmaxf(m1, __shfl_xor_sync(0xffffffffu, m1, 1));
    m1 = fmaxf(m1, __shfl_xor_sync(0xffffffffu, m1, 2));

    float l0 = 0.f, l1 = 0.f;
    #pragma unroll
    for (int ct = 0; ct < 16; ct++) {
        int c = ct * 8 + 2 * tig;
        bool v0 = (c >= lo) && (c < hi);
        bool v1 = (c + 1 >= lo) && (c + 1 < hi);
        float e0 = v0 ? __expf(sacc[ct][0] - m0) : 0.f;
        float e1 = v1 ? __expf(sacc[ct][1] - m0) : 0.f;
        float e2 = v0 ? __expf(sacc[ct][2] - m1) : 0.f;
        float e3 = v1 ? __expf(sacc[ct][3] - m1) : 0.f;
        l0 += e0 + e1;
        l1 += e2 + e3;
        sacc[ct][0] = __uint_as_float(f2tf(e0));
        sacc[ct][1] = __uint_as_float(f2tf(e1));
        sacc[ct][2] = __uint_as_float(f2tf(e2));
        sacc[ct][3] = __uint_as_float(f2tf(e3));
    }
    l0 += __shfl_xor_sync(0xffffffffu, l0, 1);
    l0 += __shfl_xor_sync(0xffffffffu, l0, 2);
    l1 += __shfl_xor_sync(0xffffffffu, l1, 1);
    l1 += __shfl_xor_sync(0xffffffffu, l1, 2);

    // ---- P @ V with P in registers (C->A layout via k-permutation on V rows) ----
    // key mapping for tile kt: k_logical t <-> key 8kt+2t, t+4 <-> 8kt+2t+1
    //   a0 = P(r0, 8kt+2t)   = sacc[kt][0]
    //   a1 = P(r0+8, 8kt+2t) = sacc[kt][2]
    //   a2 = P(r0, 8kt+2t+1) = sacc[kt][1]
    //   a3 = P(r0+8, +1)     = sacc[kt][3]
    //   b0 = Vs[8kt+2t][n],  b1 = Vs[8kt+2t+1][n]
    float oacc[4][4];
    #pragma unroll
    for (int nt = 0; nt < 4; nt++)
        #pragma unroll
        for (int j = 0; j < 4; j++) oacc[nt][j] = 0.f;

    #pragma unroll
    for (int kt = 0; kt < 16; kt++) {
        int key0 = kt * 8 + 2 * tig;
        uint32_t a0 = __float_as_uint(sacc[kt][0]);
        uint32_t a1 = __float_as_uint(sacc[kt][2]);
        uint32_t a2 = __float_as_uint(sacc[kt][1]);
        uint32_t a3 = __float_as_uint(sacc[kt][3]);
        const float* v0p = Vs + key0 * V_STRIDE + gid;
        const float* v1p = v0p + V_STRIDE;
        #pragma unroll
        for (int nt = 0; nt < 4; nt++) {
            uint32_t b0 = __float_as_uint(v0p[nt * 8]);
            uint32_t b1 = __float_as_uint(v1p[nt * 8]);
            mma_tf32(oacc[nt], a0, a1, a2, a3, b0, b1);
        }
    }

    // ---- normalize, mask invalid queries, write out ----
    float s0 = ((r0 >= lo) && (r0 < hi) && l0 > 0.f)         ? __frcp_rn(l0) : 0.f;
    float s1 = ((r0 + 8 >= lo) && (r0 + 8 < hi) && l1 > 0.f) ? __frcp_rn(l1) : 0.f;
    float* O0 = O + base + (size_t)r0 * (HEADS * DIM);
    float* O1 = O + base + (size_t)(r0 + 8) * (HEADS * DIM);
    #pragma unroll
    for (int nt = 0; nt < 4; nt++) {
        int c = nt * 8 + 2 * tig;
        *(float2*)(O0 + c) = make_float2(oacc[nt][0] * s0, oacc[nt][1] * s0);
        *(float2*)(O1 + c) = make_float2(oacc[nt][2] * s1, oacc[nt][3] * s1);
    }
}

extern "C" void kernel_launch(void* const* d_in, const int* in_sizes, int n_in,
                              void* d_out, int out_size) {
    const float* Q     = (const float*)d_in[0];
    const float* K     = (const float*)d_in[1];
    const float* V     = (const float*)d_in[2];
    const int*   scope = (const int*)d_in[3];
    (void)n_in; (void)out_size;

    int B = in_sizes[0] / (LSEQ * HEADS * DIM);  // = 2

    cudaFuncSetAttribute(bucket_attn_kernel,
                         cudaFuncAttributeMaxDynamicSharedMemorySize, SMEM_BYTES);

    dim3 grid(NB, HEADS, B);
    bucket_attn_kernel<<<grid, 256, SMEM_BYTES>>>(Q, K, V, scope, (float*)d_out);
}

// round 4
// speedup vs baseline: 1.7552x; 1.2380x over previous
#include <cuda_runtime.h>
#include <cstdint>

#define LSEQ  65536
#define HEADS 8
#define DIM   32
#define BS    128
#define NB    (LSEQ / BS)

#define QK_STRIDE 40   // floats; fragment .64 loads + staging .128 conflict-free
#define V_STRIDE  36   // floats; scalar PV B-loads conflict-free
#define SMEM_FLOATS (2 * 128 * QK_STRIDE + 128 * V_STRIDE)
#define SMEM_BYTES  (SMEM_FLOATS * 4)

// 1/sqrt(32) * log2(e): QK scores come out in the exp2 domain
#define SCALE_LOG2E ((float)(0.17677669529663687 * 1.4426950408889634))

// round-to-nearest fp32 -> tf32 (kept in 32-bit container)
__device__ __forceinline__ uint32_t f2tf(float x) {
    uint32_t u;
    asm("cvt.rna.tf32.f32 %0, %1;" : "=r"(u) : "f"(x));
    return u;
}

__device__ __forceinline__ float ex2(float x) {
    float r;
    asm("ex2.approx.ftz.f32 %0, %1;" : "=f"(r) : "f"(x));
    return r;
}

__device__ __forceinline__ void mma_tf32(float* d,
                                         uint32_t a0, uint32_t a1, uint32_t a2, uint32_t a3,
                                         uint32_t b0, uint32_t b1) {
    asm volatile("mma.sync.aligned.m16n8k8.row.col.f32.tf32.tf32.f32 "
                 "{%0,%1,%2,%3}, {%4,%5,%6,%7}, {%8,%9}, {%0,%1,%2,%3};"
                 : "+f"(d[0]), "+f"(d[1]), "+f"(d[2]), "+f"(d[3])
                 : "r"(a0), "r"(a1), "r"(a2), "r"(a3), "r"(b0), "r"(b1));
}

__global__ void __launch_bounds__(256, 2)
bucket_attn_kernel(const float* __restrict__ Q, const float* __restrict__ K,
                   const float* __restrict__ V, const int* __restrict__ scope,
                   float* __restrict__ O) {
    extern __shared__ float smem[];
    float* Qs = smem;                       // [128][40]
    float* Ks = Qs + 128 * QK_STRIDE;       // [128][40]
    float* Vs = Ks + 128 * QK_STRIDE;       // [128][36]  natural [key][d]

    const int bucket = blockIdx.x;
    const int h      = blockIdx.y;
    const int b      = blockIdx.z;
    const int tid    = threadIdx.x;

    const int sidx = (b * NB + bucket) * 2;
    const int lo = scope[sidx]     - bucket * BS;
    const int hi = scope[sidx + 1] - bucket * BS;
    const bool full = (lo <= 0) && (hi >= BS);   // uniform per CTA

    const size_t base = ((size_t)(b * LSEQ + bucket * BS) * HEADS + h) * DIM;
    const float4* Qg = (const float4*)(Q + base);
    const float4* Kg = (const float4*)(K + base);
    const float4* Vg = (const float4*)(V + base);
    const int rs4 = HEADS * DIM / 4;  // 64 float4 between rows

    // ---- Stage Q,K,V into SMEM (tf32-rounded; Q pre-scaled into exp2 domain) ----
    #pragma unroll
    for (int it = 0; it < 4; it++) {
        int idx = tid + it * 256;        // 0..1023 (128 rows x 8 float4)
        int row = idx >> 3, c4 = idx & 7;
        float4 q = Qg[row * rs4 + c4];
        float4 k = Kg[row * rs4 + c4];
        float4 v = Vg[row * rs4 + c4];
        uint4 qt = make_uint4(f2tf(q.x * SCALE_LOG2E), f2tf(q.y * SCALE_LOG2E),
                              f2tf(q.z * SCALE_LOG2E), f2tf(q.w * SCALE_LOG2E));
        uint4 kt = make_uint4(f2tf(k.x), f2tf(k.y), f2tf(k.z), f2tf(k.w));
        uint4 vt = make_uint4(f2tf(v.x), f2tf(v.y), f2tf(v.z), f2tf(v.w));
        *(uint4*)(Qs + row * QK_STRIDE + c4 * 4) = qt;
        *(uint4*)(Ks + row * QK_STRIDE + c4 * 4) = kt;
        *(uint4*)(Vs + row * V_STRIDE  + c4 * 4) = vt;
    }
    __syncthreads();

    const int lane = tid & 31;
    const int w    = tid >> 5;
    const int gid  = lane >> 2;     // 0..7
    const int tig  = lane & 3;      // 0..3
    const int r0   = w * 16 + gid;  // this lane's rows: r0 and r0+8

    // ---- QK^T : scores[16 rows][128 cols], per-warp (k-permuted operands) ----
    float sacc[16][4];
    #pragma unroll
    for (int ct = 0; ct < 16; ct++)
        #pragma unroll
        for (int j = 0; j < 4; j++) sacc[ct][j] = 0.f;

    #pragma unroll
    for (int ks = 0; ks < 4; ks++) {
        int kc = ks * 8 + 2 * tig;
        float2 alo = *(const float2*)(Qs + r0 * QK_STRIDE + kc);        // (a0, a2)
        float2 ahi = *(const float2*)(Qs + (r0 + 8) * QK_STRIDE + kc);  // (a1, a3)
        uint32_t a0 = __float_as_uint(alo.x), a2 = __float_as_uint(alo.y);
        uint32_t a1 = __float_as_uint(ahi.x), a3 = __float_as_uint(ahi.y);
        #pragma unroll
        for (int ct = 0; ct < 16; ct++) {
            int kr = ct * 8 + gid;
            float2 bp = *(const float2*)(Ks + kr * QK_STRIDE + kc);     // (b0, b1)
            mma_tf32(sacc[ct], a0, a1, a2, a3,
                     __float_as_uint(bp.x), __float_as_uint(bp.y));
        }
    }

    // ---- softmax in exp2 domain (quad shuffles; unnormalized; exact fp32 sums) ----
    float m0 = -1e30f, m1 = -1e30f;
    if (full) {
        #pragma unroll
        for (int ct = 0; ct < 16; ct++) {
            m0 = fmaxf(m0, fmaxf(sacc[ct][0], sacc[ct][1]));
            m1 = fmaxf(m1, fmaxf(sacc[ct][2], sacc[ct][3]));
        }
    } else {
        #pragma unroll
        for (int ct = 0; ct < 16; ct++) {
            int c = ct * 8 + 2 * tig;
            bool v0 = (c >= lo) && (c < hi);
            bool v1 = (c + 1 >= lo) && (c + 1 < hi);
            if (v0) { m0 = fmaxf(m0, sacc[ct][0]); m1 = fmaxf(m1, sacc[ct][2]); }
            if (v1) { m0 = fmaxf(m0, sacc[ct][1]); m1 = fmaxf(m1, sacc[ct][3]); }
        }
    }
    m0 = fmaxf(m0, __shfl_xor_sync(0xffffffffu, m0, 1));
    m0 = fmaxf(m0, __shfl_xor_sync(0xffffffffu, m0, 2));
    m1 = fmaxf(m1, __shfl_xor_sync(0xffffffffu, m1, 1));
    m1 = fmaxf(m1, __shfl_xor_sync(0xffffffffu, m1, 2));

    float l0 = 0.f, l1 = 0.f;
    if (full) {
        #pragma unroll
        for (int ct = 0; ct < 16; ct++) {
            float e0 = ex2(sacc[ct][0] - m0);
            float e1 = ex2(sacc[ct][1] - m0);
            float e2 = ex2(sacc[ct][2] - m1);
            float e3 = ex2(sacc[ct][3] - m1);
            l0 += e0 + e1;
            l1 += e2 + e3;
            sacc[ct][0] = __uint_as_float(f2tf(e0));
            sacc[ct][1] = __uint_as_float(f2tf(e1));
            sacc[ct][2] = __uint_as_float(f2tf(e2));
            sacc[ct][3] = __uint_as_float(f2tf(e3));
        }
    } else {
        #pragma unroll
        for (int ct = 0; ct < 16; ct++) {
            int c = ct * 8 + 2 * tig;
            bool v0 = (c >= lo) && (c < hi);
            bool v1 = (c + 1 >= lo) && (c + 1 < hi);
            float e0 = v0 ? ex2(sacc[ct][0] - m0) : 0.f;
            float e1 = v1 ? ex2(sacc[ct][1] - m0) : 0.f;
            float e2 = v0 ? ex2(sacc[ct][2] - m1) : 0.f;
            float e3 = v1 ? ex2(sacc[ct][3] - m1) : 0.f;
            l0 += e0 + e1;
            l1 += e2 + e3;
            sacc[ct][0] = __uint_as_float(f2tf(e0));
            sacc[ct][1] = __uint_as_float(f2tf(e1));
            sacc[ct][2] = __uint_as_float(f2tf(e2));
            sacc[ct][3] = __uint_as_float(f2tf(e3));
        }
    }
    l0 += __shfl_xor_sync(0xffffffffu, l0, 1);
    l0 += __shfl_xor_sync(0xffffffffu, l0, 2);
    l1 += __shfl_xor_sync(0xffffffffu, l1, 1);
    l1 += __shfl_xor_sync(0xffffffffu, l1, 2);

    // ---- P @ V with P in registers (C->A layout via k-permutation on V rows) ----
    float oacc[4][4];
    #pragma unroll
    for (int nt = 0; nt < 4; nt++)
        #pragma unroll
        for (int j = 0; j < 4; j++) oacc[nt][j] = 0.f;

    #pragma unroll
    for (int kt = 0; kt < 16; kt++) {
        int key0 = kt * 8 + 2 * tig;
        uint32_t a0 = __float_as_uint(sacc[kt][0]);
        uint32_t a1 = __float_as_uint(sacc[kt][2]);
        uint32_t a2 = __float_as_uint(sacc[kt][1]);
        uint32_t a3 = __float_as_uint(sacc[kt][3]);
        const float* v0p = Vs + key0 * V_STRIDE + gid;
        const float* v1p = v0p + V_STRIDE;
        #pragma unroll
        for (int nt = 0; nt < 4; nt++) {
            uint32_t b0 = __float_as_uint(v0p[nt * 8]);
            uint32_t b1 = __float_as_uint(v1p[nt * 8]);
            mma_tf32(oacc[nt], a0, a1, a2, a3, b0, b1);
        }
    }

    // ---- normalize, mask invalid queries, write out ----
    float s0 = ((r0 >= lo) && (r0 < hi) && l0 > 0.f)         ? __frcp_rn(l0) : 0.f;
    float s1 = ((r0 + 8 >= lo) && (r0 + 8 < hi) && l1 > 0.f) ? __frcp_rn(l1) : 0.f;
    float* O0 = O + base + (size_t)r0 * (HEADS * DIM);
    float* O1 = O + base + (size_t)(r0 + 8) * (HEADS * DIM);
    #pragma unroll
    for (int nt = 0; nt < 4; nt++) {
        int c = nt * 8 + 2 * tig;
        *(float2*)(O0 + c) = make_float2(oacc[nt][0] * s0, oacc[nt][1] * s0);
        *(float2*)(O1 + c) = make_float2(oacc[nt][2] * s1, oacc[nt][3] * s1);
    }
}

extern "C" void kernel_launch(void* const* d_in, const int* in_sizes, int n_in,
                              void* d_out, int out_size) {
    const float* Q     = (const float*)d_in[0];
    const float* K     = (const float*)d_in[1];
    const float* V     = (const float*)d_in[2];
    const int*   scope = (const int*)d_in[3];
    (void)n_in; (void)out_size;

    int B = in_sizes[0] / (LSEQ * HEADS * DIM);  // = 2

    cudaFuncSetAttribute(bucket_attn_kernel,
                         cudaFuncAttributeMaxDynamicSharedMemorySize, SMEM_BYTES);

    dim3 grid(NB, HEADS, B);
    bucket_attn_kernel<<<grid, 256, SMEM_BYTES>>>(Q, K, V, scope, (float*)d_out);
}